// round 2
// baseline (speedup 1.0000x reference)
#include <cuda_runtime.h>
#include <cuda_bf16.h>
#include <cstdint>

// ---------------------------------------------------------------------------
// Fused ConvTranspose3d(3->16,k3,s2,p1) * 0.5 -> AvgPool(2) -> +bias  reduces
// to a dense stride-1 VALID conv with a 2x2x2 kernel:
//   out[n,oc,z,y,w] = sum_ic sum_{a,b,c in {0,1}} x[n,ic,z+a,y+b,w+c]*fw[oc,ic,a,b,c] + fb[oc]
//   fw = fold(conv_weight) * 0.0625,  fb = 0.5*conv_bias + ext_bias
// fold along each axis: index0 -> taps(1)+(2), index1 -> tap(0)
// x: (4,3,128,128,128) fp32, out: (4,16,127,127,127) fp32
// ---------------------------------------------------------------------------

#define IC 3
#define OC 16
#define DIN 128
#define DOUT 127

// input strides (floats)
#define XNS 6291456   // 3*128^3
#define XCS 2097152   // 128^3
#define XZS 16384     // 128^2
// output strides (floats)
#define OCS 2048383   // 127^3
#define ONS 32774128  // 16*127^3
#define OZS 16129     // 127^2
#define OYS 127

// Folded weights as (oc even, oc odd) pairs: g_w[pair(8)][tap(24)][half(2)]
// tap = ((ic*2+kd)*2+kh)*2+kw
// NOTE: accessed via 64-bit loads -> must be >=8B aligned (LDG.64 traps otherwise)
__device__ __align__(16) float g_w[8 * 24 * 2];
__device__ __align__(16) float g_b[16];  // ull load at pair p -> (fb[2p], fb[2p+1])

__global__ void fold_weights_kernel(const float* __restrict__ cw,
                                    const float* __restrict__ cb,
                                    const float* __restrict__ eb) {
    int i = blockIdx.x * blockDim.x + threadIdx.x;
    if (i < 384) {
        int oc = i / 24, tap = i % 24;
        int ic = tap >> 3;
        int kd = (tap >> 2) & 1, kh = (tap >> 1) & 1, kw = tap & 1;
        float s = 0.f;
        // fold index 0 -> taps {1,2}; index 1 -> tap {0}
        int plo = kd ? 0 : 1, phi = kd ? 0 : 2;
        int qlo = kh ? 0 : 1, qhi = kh ? 0 : 2;
        int rlo = kw ? 0 : 1, rhi = kw ? 0 : 2;
        for (int p = plo; p <= phi; ++p)
            for (int q = qlo; q <= qhi; ++q)
                for (int r = rlo; r <= rhi; ++r)
                    // conv_weight shape (3,16,3,3,3)
                    s += cw[ic * 432 + oc * 27 + p * 9 + q * 3 + r];
        g_w[(oc >> 1) * 48 + tap * 2 + (oc & 1)] = s * 0.0625f;
    } else if (i < 400) {
        int oc = i - 384;
        g_b[oc] = cb[oc] * 0.5f + eb[oc];
    }
}

// ---- packed fp32x2 helpers (Blackwell FFMA2 path; ptxas won't emit from C++)
typedef unsigned long long ull;

__device__ __forceinline__ void ffma2(ull& d, ull a, ull b) {
    asm("fma.rn.f32x2 %0, %1, %2, %0;" : "+l"(d) : "l"(a), "l"(b));
}
__device__ __forceinline__ ull rep2(float v) {
    ull r; unsigned u = __float_as_uint(v);
    asm("mov.b64 %0, {%1, %1};" : "=l"(r) : "r"(u));
    return r;
}
__device__ __forceinline__ float lo2(ull a) { return __uint_as_float((unsigned)a); }
__device__ __forceinline__ float hi2(ull a) { return __uint_as_float((unsigned)(a >> 32)); }

#define ROWW (DIN + 4)   // pad so r[4] at w0=124 stays in-bounds (value unused)

// Block: 128 threads = 32 (w, 4 outputs each) x 4 (oc groups of 4)
// Grid:  (16 h-tiles, 127 d, 4 n)
__global__ void __launch_bounds__(128, 3)
conv2x2x2_kernel(const float* __restrict__ x, float* __restrict__ out) {
    __shared__ float tile[IC][2][9][ROWW];   // 28512 B

    const int tid = threadIdx.x;
    const int tw = tid & 31;        // w group
    const int og = tid >> 5;        // oc group: oc = 4*og .. 4*og+3
    const int ht = blockIdx.x;
    const int d  = blockIdx.y;
    const int n  = blockIdx.z;
    const int h0 = ht * 8;

    // ---- load x tile: 3 ic x 2 d-planes x 9 h rows x 128 w
    {
        const float* xb = x + (size_t)n * XNS + (size_t)d * XZS;
        for (int i = tid; i < 54 * 32; i += 128) {
            int row = i >> 5;
            int col = (i & 31) << 2;
            int ic  = row / 18;
            int rem = row - ic * 18;
            int dz  = rem / 9;
            int hy  = rem - dz * 9;
            int gy  = h0 + hy;
            if (gy > 127) gy = 127;   // clamp (last tile); rows unused by stores
            const float4 v = *(const float4*)(xb + (size_t)ic * XCS +
                                              (size_t)dz * XZS + gy * DIN + col);
            *(float4*)&tile[ic][dz][hy][col] = v;
        }
    }

    // ---- load this thread's 48 weight pairs (uniform per warp -> broadcast)
    ull W0[24], W1[24];
    {
        const ull* wp = (const ull*)g_w;
        const int p0 = 2 * og, p1 = 2 * og + 1;
#pragma unroll
        for (int j = 0; j < 24; ++j) {
            W0[j] = wp[p0 * 24 + j];   // halves: (oc=4og,   oc=4og+1)
            W1[j] = wp[p1 * 24 + j];   // halves: (oc=4og+2, oc=4og+3)
        }
    }
    const ull FB0 = ((const ull*)g_b)[2 * og];
    const ull FB1 = ((const ull*)g_b)[2 * og + 1];

    __syncthreads();

    const int w0 = tw * 4;
    float* obase = out + (size_t)n * ONS + (size_t)(4 * og) * OCS +
                   (size_t)d * OZS + w0;

    for (int hl = 0; hl < 8; ++hl) {
        const int h = h0 + hl;
        if (h >= DOUT) break;      // uniform across block

        ull a00 = FB0, a01 = FB1;  // w0+0 : (oc0,oc1),(oc2,oc3)
        ull a10 = FB0, a11 = FB1;  // w0+1
        ull a20 = FB0, a21 = FB1;  // w0+2
        ull a30 = FB0, a31 = FB1;  // w0+3

#pragma unroll
        for (int ic = 0; ic < IC; ++ic)
#pragma unroll
        for (int kd = 0; kd < 2; ++kd)
#pragma unroll
        for (int kh = 0; kh < 2; ++kh) {
            const float* r = &tile[ic][kd][hl + kh][w0];
            const float4 xa = *(const float4*)r;   // 16B-aligned (w0 = 4*tw)
            const float  x4 = r[4];                // in-bounds via row padding
            const ull X0 = rep2(xa.x), X1 = rep2(xa.y), X2 = rep2(xa.z),
                      X3 = rep2(xa.w), X4 = rep2(x4);
            const int tb = ((ic * 2 + kd) * 2 + kh) * 2;
            const ull wa0 = W0[tb], wb0 = W0[tb + 1];
            const ull wa1 = W1[tb], wb1 = W1[tb + 1];

            ffma2(a00, X0, wa0); ffma2(a00, X1, wb0);
            ffma2(a01, X0, wa1); ffma2(a01, X1, wb1);
            ffma2(a10, X1, wa0); ffma2(a10, X2, wb0);
            ffma2(a11, X1, wa1); ffma2(a11, X2, wb1);
            ffma2(a20, X2, wa0); ffma2(a20, X3, wb0);
            ffma2(a21, X2, wa1); ffma2(a21, X3, wb1);
            ffma2(a30, X3, wa0); ffma2(a30, X4, wb0);
            ffma2(a31, X3, wa1); ffma2(a31, X4, wb1);
        }

        // ---- stores: 4 oc rows x 4 w (scalar STG.32 — out row base is odd-offset)
        float* o = obase + (size_t)h * OYS;
        const bool full = (tw != 31);  // tw==31: w0=124 -> only w 124..126 valid
        // oc = 4og + 0 (lo of a*0)
        o[0] = lo2(a00); o[1] = lo2(a10); o[2] = lo2(a20); if (full) o[3] = lo2(a30);
        // oc = 4og + 1 (hi of a*0)
        {
            float* p = o + OCS;
            p[0] = hi2(a00); p[1] = hi2(a10); p[2] = hi2(a20); if (full) p[3] = hi2(a30);
        }
        // oc = 4og + 2 (lo of a*1)
        {
            float* p = o + 2 * OCS;
            p[0] = lo2(a01); p[1] = lo2(a11); p[2] = lo2(a21); if (full) p[3] = lo2(a31);
        }
        // oc = 4og + 3 (hi of a*1)
        {
            float* p = o + 3 * OCS;
            p[0] = hi2(a01); p[1] = hi2(a11); p[2] = hi2(a21); if (full) p[3] = hi2(a31);
        }
    }
}

extern "C" void kernel_launch(void* const* d_in, const int* in_sizes, int n_in,
                              void* d_out, int out_size) {
    const float* x  = (const float*)d_in[0];
    const float* cw = (const float*)d_in[1];
    const float* cb = (const float*)d_in[2];
    const float* eb = (const float*)d_in[3];
    float* out = (float*)d_out;

    fold_weights_kernel<<<1, 512>>>(cw, cb, eb);

    dim3 grid(16, DOUT, 4);   // h-tiles, d, n
    conv2x2x2_kernel<<<grid, 128>>>(x, out);
}

// round 3
// speedup vs baseline: 1.0370x; 1.0370x over previous
#include <cuda_runtime.h>
#include <cuda_bf16.h>
#include <cstdint>

// ---------------------------------------------------------------------------
// Fused ConvTranspose3d(3->16,k3,s2,p1) * 0.5 -> AvgPool(2) -> +bias  reduces
// to a dense stride-1 VALID conv with a 2x2x2 kernel:
//   out[n,oc,z,y,w] = sum_ic sum_{a,b,c} x[n,ic,z+a,y+b,w+c]*fw[oc,ic,a,b,c] + fb[oc]
//   fw = fold(conv_weight) * 0.0625,  fb = 0.5*conv_bias + ext_bias
// x: (4,3,128,128,128) fp32, out: (4,16,127,127,127) fp32
// ---------------------------------------------------------------------------

#define IC 3
#define OC 16
#define DIN 128
#define DOUT 127

// input strides (floats)
#define XNS 6291456   // 3*128^3
#define XCS 2097152   // 128^3
#define XZS 16384     // 128^2
// output strides (floats)
#define OCS 2048383   // 127^3
#define ONS 32774128  // 16*127^3
#define OZS 16129     // 127^2
#define OYS 127

// Folded weights as (oc even, oc odd) pairs: g_w[pair(8)][tap(24)][half(2)]
// tap = ((ic*2+kd)*2+kh)*2+kw ; accessed via 64-bit loads -> 16B aligned
__device__ __align__(16) float g_w[8 * 24 * 2];
__device__ __align__(16) float g_b[16];

__global__ void fold_weights_kernel(const float* __restrict__ cw,
                                    const float* __restrict__ cb,
                                    const float* __restrict__ eb) {
    int i = blockIdx.x * blockDim.x + threadIdx.x;
    if (i < 384) {
        int oc = i / 24, tap = i % 24;
        int ic = tap >> 3;
        int kd = (tap >> 2) & 1, kh = (tap >> 1) & 1, kw = tap & 1;
        float s = 0.f;
        int plo = kd ? 0 : 1, phi = kd ? 0 : 2;
        int qlo = kh ? 0 : 1, qhi = kh ? 0 : 2;
        int rlo = kw ? 0 : 1, rhi = kw ? 0 : 2;
        for (int p = plo; p <= phi; ++p)
            for (int q = qlo; q <= qhi; ++q)
                for (int r = rlo; r <= rhi; ++r)
                    s += cw[ic * 432 + oc * 27 + p * 9 + q * 3 + r];
        g_w[(oc >> 1) * 48 + tap * 2 + (oc & 1)] = s * 0.0625f;
    } else if (i < 400) {
        int oc = i - 384;
        g_b[oc] = cb[oc] * 0.5f + eb[oc];
    }
}

// ---- packed fp32x2 helpers (Blackwell FFMA2; ptxas won't emit from C++)
typedef unsigned long long ull;

__device__ __forceinline__ void ffma2(ull& d, ull a, ull b) {
    asm("fma.rn.f32x2 %0, %1, %2, %0;" : "+l"(d) : "l"(a), "l"(b));
}
__device__ __forceinline__ ull rep2(float v) {
    ull r; unsigned u = __float_as_uint(v);
    asm("mov.b64 %0, {%1, %1};" : "=l"(r) : "r"(u));
    return r;
}
__device__ __forceinline__ float lo2(ull a) { return __uint_as_float((unsigned)a); }
__device__ __forceinline__ float hi2(ull a) { return __uint_as_float((unsigned)(a >> 32)); }

// Store one oc output row segment (w0..w0+3) using STG.64 where 8B-aligned.
// par = (float-index of p) & 1, uniform across the warp.
__device__ __forceinline__ void store_row(float* p, float v0, float v1,
                                          float v2, float v3, bool full, int par) {
    if (par == 0) {                       // p is 8B aligned
        *(float2*)p = make_float2(v0, v1);
        if (full) *(float2*)(p + 2) = make_float2(v2, v3);
        else      p[2] = v2;
    } else {                              // p+1 is 8B aligned
        p[0] = v0;
        *(float2*)(p + 1) = make_float2(v1, v2);
        if (full) p[3] = v3;
    }
}

// Block: 128 threads = 32 (w, 4 outputs each) x 4 (oc groups of 4)
// Grid:  (16 h-tiles, 127 d, 4 n)
__global__ void __launch_bounds__(128, 3)
conv2x2x2_kernel(const float* __restrict__ x, float* __restrict__ out) {
    __shared__ float tile[IC][2][9][DIN];   // 27648 B

    const int tid = threadIdx.x;
    const int tw = tid & 31;        // w group
    const int og = tid >> 5;        // oc group: oc = 4*og .. 4*og+3
    const int ht = blockIdx.x;
    const int d  = blockIdx.y;
    const int n  = blockIdx.z;
    const int h0 = ht * 8;

    // ---- load x tile: 3 ic x 2 d-planes x 9 h rows x 128 w
    {
        const float* xb = x + (size_t)n * XNS + (size_t)d * XZS;
        for (int i = tid; i < 54 * 32; i += 128) {
            int row = i >> 5;
            int col = (i & 31) << 2;
            int ic  = row / 18;
            int rem = row - ic * 18;
            int dz  = rem / 9;
            int hy  = rem - dz * 9;
            int gy  = h0 + hy;
            if (gy > 127) gy = 127;   // clamp (last tile); rows unused by stores
            const float4 v = *(const float4*)(xb + (size_t)ic * XCS +
                                              (size_t)dz * XZS + gy * DIN + col);
            *(float4*)&tile[ic][dz][hy][col] = v;
        }
    }

    // ---- this thread's 48 weight pairs (warp-uniform -> broadcast loads)
    ull W0[24], W1[24];
    {
        const ull* wp = (const ull*)g_w;
        const int p0 = 2 * og, p1 = 2 * og + 1;
#pragma unroll
        for (int j = 0; j < 24; ++j) {
            W0[j] = wp[p0 * 24 + j];   // halves: (oc=4og,   oc=4og+1)
            W1[j] = wp[p1 * 24 + j];   // halves: (oc=4og+2, oc=4og+3)
        }
    }
    const ull FB0 = ((const ull*)g_b)[2 * og];
    const ull FB1 = ((const ull*)g_b)[2 * og + 1];

    __syncthreads();

    const int w0 = tw * 4;
    float* obase = out + (size_t)n * ONS + (size_t)(4 * og) * OCS +
                   (size_t)d * OZS + w0;

    for (int hl = 0; hl < 8; ++hl) {
        const int h = h0 + hl;
        if (h >= DOUT) break;      // uniform across block

        ull a00 = FB0, a01 = FB1;  // w0+0 : (oc0,oc1),(oc2,oc3)
        ull a10 = FB0, a11 = FB1;  // w0+1
        ull a20 = FB0, a21 = FB1;  // w0+2
        ull a30 = FB0, a31 = FB1;  // w0+3

#pragma unroll
        for (int ic = 0; ic < IC; ++ic)
#pragma unroll
        for (int kd = 0; kd < 2; ++kd)
#pragma unroll
        for (int kh = 0; kh < 2; ++kh) {
            const float* r = &tile[ic][kd][hl + kh][w0];
            const float4 xa = *(const float4*)r;   // 16B-aligned (w0 = 4*tw)
            // x[w0+4] = next lane's xa.x (lane 31's result only feeds the
            // masked-out w=127 output)
            const float x4 = __shfl_down_sync(0xffffffffu, xa.x, 1);
            const ull X0 = rep2(xa.x), X1 = rep2(xa.y), X2 = rep2(xa.z),
                      X3 = rep2(xa.w), X4 = rep2(x4);
            const int tb = ((ic * 2 + kd) * 2 + kh) * 2;
            const ull wa0 = W0[tb], wb0 = W0[tb + 1];
            const ull wa1 = W1[tb], wb1 = W1[tb + 1];

            ffma2(a00, X0, wa0); ffma2(a00, X1, wb0);
            ffma2(a01, X0, wa1); ffma2(a01, X1, wb1);
            ffma2(a10, X1, wa0); ffma2(a10, X2, wb0);
            ffma2(a11, X1, wa1); ffma2(a11, X2, wb1);
            ffma2(a20, X2, wa0); ffma2(a20, X3, wb0);
            ffma2(a21, X2, wa1); ffma2(a21, X3, wb1);
            ffma2(a30, X3, wa0); ffma2(a30, X4, wb0);
            ffma2(a31, X3, wa1); ffma2(a31, X4, wb1);
        }

        // ---- stores: 4 oc rows x 4 w; STG.64 where alignment allows.
        // float-index parity of row base for oc=4og+j: (j + d + h) & 1
        float* o = obase + (size_t)h * OYS;
        const bool full = (tw != 31);   // tw==31: only w 124..126 valid
        const int basep = (d + h) & 1;

        store_row(o,           lo2(a00), lo2(a10), lo2(a20), lo2(a30), full, basep);
        store_row(o + OCS,     hi2(a00), hi2(a10), hi2(a20), hi2(a30), full, basep ^ 1);
        store_row(o + 2 * OCS, lo2(a01), lo2(a11), lo2(a21), lo2(a31), full, basep);
        store_row(o + 3 * OCS, hi2(a01), hi2(a11), hi2(a21), hi2(a31), full, basep ^ 1);
    }
}

extern "C" void kernel_launch(void* const* d_in, const int* in_sizes, int n_in,
                              void* d_out, int out_size) {
    const float* x  = (const float*)d_in[0];
    const float* cw = (const float*)d_in[1];
    const float* cb = (const float*)d_in[2];
    const float* eb = (const float*)d_in[3];
    float* out = (float*)d_out;

    fold_weights_kernel<<<1, 512>>>(cw, cb, eb);

    dim3 grid(16, DOUT, 4);   // h-tiles, d, n
    conv2x2x2_kernel<<<grid, 128>>>(x, out);
}

// round 4
// speedup vs baseline: 1.2904x; 1.2444x over previous
#include <cuda_runtime.h>
#include <cuda_bf16.h>
#include <cstdint>

// ---------------------------------------------------------------------------
// Fused ConvTranspose3d(3->16,k3,s2,p1) * 0.5 -> AvgPool(2) -> +bias  reduces
// to a dense stride-1 VALID conv with a 2x2x2 kernel:
//   out[n,oc,z,y,w] = sum_ic sum_{a,b,c} x[n,ic,z+a,y+b,w+c]*fw[oc,ic,a,b,c] + fb[oc]
// x: (4,3,128,128,128) fp32, out: (4,16,127,127,127) fp32
// ---------------------------------------------------------------------------

#define IC 3
#define OC 16
#define DIN 128
#define DOUT 127

#define XNS 6291456   // 3*128^3
#define XCS 2097152   // 128^3
#define XZS 16384     // 128^2
#define OCS 2048383   // 127^3
#define ONS 32774128  // 16*127^3
#define OZS 16129     // 127^2
#define OYS 127

// Folded weights as (oc even, oc odd) pairs: g_w[pair(8)][tap(24)][half(2)]
// tap = ((ic*2+kd)*2+kh)*2+kw ; accessed via 64/128-bit loads -> 16B aligned
__device__ __align__(16) float g_w[8 * 24 * 2];
__device__ __align__(16) float g_b[16];

__global__ void fold_weights_kernel(const float* __restrict__ cw,
                                    const float* __restrict__ cb,
                                    const float* __restrict__ eb) {
    int i = blockIdx.x * blockDim.x + threadIdx.x;
    if (i < 384) {
        int oc = i / 24, tap = i % 24;
        int ic = tap >> 3;
        int kd = (tap >> 2) & 1, kh = (tap >> 1) & 1, kw = tap & 1;
        float s = 0.f;
        int plo = kd ? 0 : 1, phi = kd ? 0 : 2;
        int qlo = kh ? 0 : 1, qhi = kh ? 0 : 2;
        int rlo = kw ? 0 : 1, rhi = kw ? 0 : 2;
        for (int p = plo; p <= phi; ++p)
            for (int q = qlo; q <= qhi; ++q)
                for (int r = rlo; r <= rhi; ++r)
                    s += cw[ic * 432 + oc * 27 + p * 9 + q * 3 + r];
        g_w[(oc >> 1) * 48 + tap * 2 + (oc & 1)] = s * 0.0625f;
    } else if (i < 400) {
        int oc = i - 384;
        g_b[oc] = cb[oc] * 0.5f + eb[oc];
    }
}

// ---- packed fp32x2 helpers (Blackwell FFMA2; ptxas won't emit from C++)
typedef unsigned long long ull;

__device__ __forceinline__ void ffma2(ull& d, ull a, ull b) {
    asm("fma.rn.f32x2 %0, %1, %2, %0;" : "+l"(d) : "l"(a), "l"(b));
}
__device__ __forceinline__ ull rep2(float v) {
    ull r; unsigned u = __float_as_uint(v);
    asm("mov.b64 %0, {%1, %1};" : "=l"(r) : "r"(u));
    return r;
}
__device__ __forceinline__ float lo2(ull a) { return __uint_as_float((unsigned)a); }
__device__ __forceinline__ float hi2(ull a) { return __uint_as_float((unsigned)(a >> 32)); }

// Store one oc output row segment (w0..w0+3). par = (float index of p) & 1,
// warp-uniform. par==1 pairs lane t's v0 with lane t-1's v3 (aligned STG.64).
__device__ __forceinline__ void store_row(float* p, float v0, float v1,
                                          float v2, float v3, bool full,
                                          int par, int lane) {
    if (par == 0) {                       // p is 8B aligned
        *(float2*)p = make_float2(v0, v1);
        if (full) *(float2*)(p + 2) = make_float2(v2, v3);
        else      p[2] = v2;
    } else {                              // p+1 is 8B aligned
        float u = __shfl_up_sync(0xffffffffu, v3, 1); // lane t-1's v3
        if (lane) *(float2*)(p - 1) = make_float2(u, v0);
        else      p[0] = v0;
        *(float2*)(p + 1) = make_float2(v1, v2);
        // lane t's v3 is stored by lane t+1; lane31's v3 (w=127) is invalid.
    }
}

// Block: 128 threads = 32 (w, 4 outputs each) x 4 (oc groups of 4)
// Grid:  (16 h-tiles, 127 d, 4 n). 2 output rows per inner iteration.
__global__ void __launch_bounds__(128, 6)
conv2x2x2_kernel(const float* __restrict__ x, float* __restrict__ out) {
    __shared__ __align__(16) float tile[IC][2][9][DIN];   // 27648 B
    __shared__ __align__(16) float sW[8 * 24 * 2];        // 1536 B

    const int tid = threadIdx.x;
    const int tw = tid & 31;        // w group
    const int og = tid >> 5;        // oc group: oc = 4*og .. 4*og+3
    const int ht = blockIdx.x;
    const int d  = blockIdx.y;
    const int n  = blockIdx.z;
    const int h0 = ht * 8;

    // ---- copy folded weights to smem (192 ull)
    {
        const ull* gw = (const ull*)g_w;
        ull* sw = (ull*)sW;
        if (tid < 64) { sw[tid] = gw[tid]; sw[tid + 64] = gw[tid + 64]; }
        else if (tid < 128) { sw[tid + 64] = gw[tid + 64]; }
    }

    // ---- load x tile: 3 ic x 2 d-planes x 9 h rows x 128 w
    {
        const float* xb = x + (size_t)n * XNS + (size_t)d * XZS;
        for (int i = tid; i < 54 * 32; i += 128) {
            int row = i >> 5;
            int col = (i & 31) << 2;
            int ic  = row / 18;
            int rem = row - ic * 18;
            int dz  = rem / 9;
            int hy  = rem - dz * 9;
            int gy  = h0 + hy;
            if (gy > 127) gy = 127;   // clamp (last tile); rows unused by stores
            const float4 v = *(const float4*)(xb + (size_t)ic * XCS +
                                              (size_t)dz * XZS + gy * DIN + col);
            *(float4*)&tile[ic][dz][hy][col] = v;
        }
    }

    const ull FB0 = ((const ull*)g_b)[2 * og];       // uniform LDG, aligned
    const ull FB1 = ((const ull*)g_b)[2 * og + 1];

    __syncthreads();

    const int w0 = tw * 4;
    const float* wp0 = &sW[(2 * og) * 48];
    const float* wp1 = &sW[(2 * og + 1) * 48];
    float* obase = out + (size_t)n * ONS + (size_t)(4 * og) * OCS +
                   (size_t)d * OZS + w0;

    for (int hl = 0; hl < 8; hl += 2) {
        const int h = h0 + hl;
        if (h >= DOUT) break;      // uniform across block

        // accumulators for 2 output rows, oc-packed
        ull A00 = FB0, A01 = FB1, A10 = FB0, A11 = FB1;   // row h
        ull A20 = FB0, A21 = FB1, A30 = FB0, A31 = FB1;
        ull B00 = FB0, B01 = FB1, B10 = FB0, B11 = FB1;   // row h+1
        ull B20 = FB0, B21 = FB1, B30 = FB0, B31 = FB1;

#pragma unroll 1
        for (int ickd = 0; ickd < 6; ++ickd) {
            const int ic = ickd >> 1, kd = ickd & 1;
            const float* rowb = &tile[ic][kd][hl][w0];

            // weights for this (ic,kd): kh0 pair-block, kh1 pair-block
            const int fo = ickd * 8;                // float offset = 2*tb0
            const ulonglong2 w0k0 = *(const ulonglong2*)&wp0[fo];     // wa0,wb0 kh0
            const ulonglong2 w0k1 = *(const ulonglong2*)&wp0[fo + 4]; // wa0,wb0 kh1
            const ulonglong2 w1k0 = *(const ulonglong2*)&wp1[fo];     // wa1,wb1 kh0
            const ulonglong2 w1k1 = *(const ulonglong2*)&wp1[fo + 4];

#pragma unroll
            for (int r = 0; r < 3; ++r) {
                const float* rp = rowb + r * DIN;
                const float4 xa = *(const float4*)rp;           // 16B aligned
                const float  x4 = __shfl_down_sync(0xffffffffu, xa.x, 1);
                const ull X0 = rep2(xa.x), X1 = rep2(xa.y), X2 = rep2(xa.z),
                          X3 = rep2(xa.w), X4 = rep2(x4);

                if (r < 2) {   // kh=0 contribution to row r
                    ull &a0 = (r == 0) ? A00 : B00, &a1 = (r == 0) ? A01 : B01;
                    ull &b0 = (r == 0) ? A10 : B10, &b1 = (r == 0) ? A11 : B11;
                    ull &c0 = (r == 0) ? A20 : B20, &c1 = (r == 0) ? A21 : B21;
                    ull &d0 = (r == 0) ? A30 : B30, &d1 = (r == 0) ? A31 : B31;
                    ffma2(a0, X0, w0k0.x); ffma2(a0, X1, w0k0.y);
                    ffma2(a1, X0, w1k0.x); ffma2(a1, X1, w1k0.y);
                    ffma2(b0, X1, w0k0.x); ffma2(b0, X2, w0k0.y);
                    ffma2(b1, X1, w1k0.x); ffma2(b1, X2, w1k0.y);
                    ffma2(c0, X2, w0k0.x); ffma2(c0, X3, w0k0.y);
                    ffma2(c1, X2, w1k0.x); ffma2(c1, X3, w1k0.y);
                    ffma2(d0, X3, w0k0.x); ffma2(d0, X4, w0k0.y);
                    ffma2(d1, X3, w1k0.x); ffma2(d1, X4, w1k0.y);
                }
                if (r >= 1) {  // kh=1 contribution to row r-1
                    ull &a0 = (r == 1) ? A00 : B00, &a1 = (r == 1) ? A01 : B01;
                    ull &b0 = (r == 1) ? A10 : B10, &b1 = (r == 1) ? A11 : B11;
                    ull &c0 = (r == 1) ? A20 : B20, &c1 = (r == 1) ? A21 : B21;
                    ull &d0 = (r == 1) ? A30 : B30, &d1 = (r == 1) ? A31 : B31;
                    ffma2(a0, X0, w0k1.x); ffma2(a0, X1, w0k1.y);
                    ffma2(a1, X0, w1k1.x); ffma2(a1, X1, w1k1.y);
                    ffma2(b0, X1, w0k1.x); ffma2(b0, X2, w0k1.y);
                    ffma2(b1, X1, w1k1.x); ffma2(b1, X2, w1k1.y);
                    ffma2(c0, X2, w0k1.x); ffma2(c0, X3, w0k1.y);
                    ffma2(c1, X2, w1k1.x); ffma2(c1, X3, w1k1.y);
                    ffma2(d0, X3, w0k1.x); ffma2(d0, X4, w0k1.y);
                    ffma2(d1, X3, w1k1.x); ffma2(d1, X4, w1k1.y);
                }
            }
        }

        // ---- stores: 2 rows x 4 oc; float-index parity of base: (j+d+h)&1
        const bool full = (tw != 31);   // tw==31: only w 124..126 valid
        {
            float* o = obase + (size_t)h * OYS;
            const int bp = (d + h) & 1;
            store_row(o,           lo2(A00), lo2(A10), lo2(A20), lo2(A30), full, bp,     tw);
            store_row(o + OCS,     hi2(A00), hi2(A10), hi2(A20), hi2(A30), full, bp ^ 1, tw);
            store_row(o + 2 * OCS, lo2(A01), lo2(A11), lo2(A21), lo2(A31), full, bp,     tw);
            store_row(o + 3 * OCS, hi2(A01), hi2(A11), hi2(A21), hi2(A31), full, bp ^ 1, tw);
        }
        if (h + 1 < DOUT) {
            float* o = obase + (size_t)(h + 1) * OYS;
            const int bp = (d + h + 1) & 1;
            store_row(o,           lo2(B00), lo2(B10), lo2(B20), lo2(B30), full, bp,     tw);
            store_row(o + OCS,     hi2(B00), hi2(B10), hi2(B20), hi2(B30), full, bp ^ 1, tw);
            store_row(o + 2 * OCS, lo2(B01), lo2(B11), lo2(B21), lo2(B31), full, bp,     tw);
            store_row(o + 3 * OCS, hi2(B01), hi2(B11), hi2(B21), hi2(B31), full, bp ^ 1, tw);
        }
    }
}

extern "C" void kernel_launch(void* const* d_in, const int* in_sizes, int n_in,
                              void* d_out, int out_size) {
    const float* x  = (const float*)d_in[0];
    const float* cw = (const float*)d_in[1];
    const float* cb = (const float*)d_in[2];
    const float* eb = (const float*)d_in[3];
    float* out = (float*)d_out;

    fold_weights_kernel<<<1, 512>>>(cw, cb, eb);

    dim3 grid(16, DOUT, 4);   // h-tiles, d, n
    conv2x2x2_kernel<<<grid, 128>>>(x, out);
}